// round 7
// baseline (speedup 1.0000x reference)
#include <cuda_runtime.h>

#define NBATCH   4
#define NPTS     8192
#define THREADS  256
#define QPT      4                       // queries per thread
#define QBLK     (THREADS * QPT)         // 1024 queries per block
#define CHUNKS   (NPTS / QBLK)           // 8 query chunks
#define SLICES   32                      // db split
#define DBS      (NPTS / SLICES)         // 256 db points per block
#define GROUPS   (2 * NBATCH)            // 8 (dir,b) groups
#define BLOCKS_PER_GROUP (CHUNKS * SLICES)    // 256

// Per-query clamped slice-min: [group][slice][query]. Every slot is
// overwritten each launch -> deterministic, no init needed. (8 MB)
__device__ float        g_min[GROUPS][SLICES][NPTS];
__device__ float        g_groupsum[GROUPS];
__device__ unsigned int g_cnt[GROUPS];   // zero-init; reset by final finisher
__device__ unsigned int g_cnt2;          // zero-init; reset by final finisher

typedef unsigned long long ull;

__device__ __forceinline__ ull ffma2(ull a, ull b, ull c) {
    ull d;
    asm("fma.rn.f32x2 %0, %1, %2, %3;" : "=l"(d) : "l"(a), "l"(b), "l"(c));
    return d;
}
__device__ __forceinline__ ull pack2(float lo, float hi) {
    ull d;
    asm("mov.b64 %0, {%1, %2};" : "=l"(d) : "f"(lo), "f"(hi));
    return d;
}
__device__ __forceinline__ float2 unpack2(ull v) {
    float2 r;
    asm("mov.b64 {%0, %1}, %2;" : "=f"(r.x), "=f"(r.y) : "l"(v));
    return r;
}

__global__ __launch_bounds__(THREADS, 3)
void chamfer_main(const float* __restrict__ rec,
                  const float* __restrict__ data,
                  float* __restrict__ out) {
    __shared__ float s0[DBS];
    __shared__ float s1[DBS];
    __shared__ float s2[DBS];
    __shared__ float sn[DBS];
    __shared__ float red[THREADS];
    __shared__ int   s_flag;

    const int tid   = threadIdx.x;
    const int slice = blockIdx.x & (SLICES - 1);
    const int chunk = blockIdx.x >> 5;            // 0..CHUNKS-1
    const int b     = blockIdx.y;
    const int dir   = blockIdx.z;
    const int group = dir * NBATCH + b;

    // dir 0: queries = rec, database = data   (rec_dist)
    // dir 1: queries = data, database = rec   (data_dist)
    const float* __restrict__ qry = dir ? data : rec;
    const float* __restrict__ db  = dir ? rec  : data;

    // ---- Load this db slice into SMEM (SoA + precomputed norms) ----
    const float* dbb = db + ((size_t)b * NPTS + slice * DBS) * 3;
    if (tid < DBS) {
        float x = dbb[3 * tid + 0];
        float y = dbb[3 * tid + 1];
        float z = dbb[3 * tid + 2];
        s0[tid] = x;
        s1[tid] = y;
        s2[tid] = z;
        sn[tid] = fmaf(x, x, fmaf(y, y, z * z));
    }

    // ---- Per-thread query points (4, coalesced across warp) ----
    float q2[QPT];
    ull A0[QPT], A1[QPT], A2[QPT];
    #pragma unroll
    for (int q = 0; q < QPT; ++q) {
        int qi = chunk * QBLK + q * THREADS + tid;
        const float* qp = qry + ((size_t)b * NPTS + qi) * 3;
        float qx = qp[0], qy = qp[1], qz = qp[2];
        q2[q] = fmaf(qx, qx, fmaf(qy, qy, qz * qz));
        A0[q] = pack2(-2.0f * qx, -2.0f * qx);
        A1[q] = pack2(-2.0f * qy, -2.0f * qy);
        A2[q] = pack2(-2.0f * qz, -2.0f * qz);
    }

    __syncthreads();

    // ---- Main loop: min_j ( ||y_j||^2 - 2 x . y_j )
    //      4 db points per step (broadcast LDS.128), 4 queries per thread ----
    float m0[QPT], m1[QPT], m2[QPT], m3[QPT];
    #pragma unroll
    for (int q = 0; q < QPT; ++q) { m0[q] = m1[q] = m2[q] = m3[q] = 1e30f; }

    #pragma unroll 1
    for (int j = 0; j < DBS; j += 4) {
        ulonglong2 p0 = *reinterpret_cast<const ulonglong2*>(s0 + j);
        ulonglong2 p1 = *reinterpret_cast<const ulonglong2*>(s1 + j);
        ulonglong2 p2 = *reinterpret_cast<const ulonglong2*>(s2 + j);
        ulonglong2 pn = *reinterpret_cast<const ulonglong2*>(sn + j);

        #pragma unroll
        for (int q = 0; q < QPT; ++q) {
            ull accA = ffma2(A2[q], p2.x, pn.x);
            accA     = ffma2(A1[q], p1.x, accA);
            accA     = ffma2(A0[q], p0.x, accA);

            ull accB = ffma2(A2[q], p2.y, pn.y);
            accB     = ffma2(A1[q], p1.y, accB);
            accB     = ffma2(A0[q], p0.y, accB);

            float2 fa = unpack2(accA);
            float2 fb = unpack2(accB);
            m0[q] = fminf(m0[q], fa.x);
            m1[q] = fminf(m1[q], fa.y);
            m2[q] = fminf(m2[q], fb.x);
            m3[q] = fminf(m3[q], fb.y);
        }
    }

    // ---- Per-query clamped slice-min -> global slot (coalesced stores) ----
    const int base = chunk * QBLK + tid;
    #pragma unroll
    for (int q = 0; q < QPT; ++q) {
        float mmin = fminf(fminf(m0[q], m1[q]), fminf(m2[q], m3[q]));
        float dist = fmaxf(q2[q] + mmin, 0.0f);   // clamp commutes with min
        g_min[group][slice][base + q * THREADS] = dist;
    }

    // ---- Fused reduce: last block of each group reduces that group ----
    if (tid == 0) {
        __threadfence();
        unsigned int t = atomicAdd(&g_cnt[group], 1u);
        s_flag = (t == BLOCKS_PER_GROUP - 1) ? 1 : 0;
    }
    __syncthreads();

    if (s_flag) {
        __threadfence();   // acquire: other blocks' g_min writes are visible
        float s = 0.0f;
        for (int q = tid * 4; q < NPTS; q += THREADS * 4) {
            float4 m = *reinterpret_cast<const float4*>(&g_min[group][0][q]);
            #pragma unroll
            for (int e = 1; e < SLICES; ++e) {
                float4 v = *reinterpret_cast<const float4*>(&g_min[group][e][q]);
                m.x = fminf(m.x, v.x);
                m.y = fminf(m.y, v.y);
                m.z = fminf(m.z, v.z);
                m.w = fminf(m.w, v.w);
            }
            s += (m.x + m.y) + (m.z + m.w);
        }
        red[tid] = s;
        __syncthreads();
        #pragma unroll
        for (int st = THREADS / 2; st > 0; st >>= 1) {
            if (tid < st) red[tid] += red[tid + st];
            __syncthreads();
        }
        if (tid == 0) {
            g_groupsum[group] = red[0];
            __threadfence();
            unsigned int t2 = atomicAdd(&g_cnt2, 1u);
            if (t2 == GROUPS - 1) {
                __threadfence();
                float total = 0.0f;
                #pragma unroll
                for (int bb = 0; bb < NBATCH; ++bb) {
                    float mean_rec = g_groupsum[0 * NBATCH + bb] * (1.0f / NPTS);
                    float mean_dat = g_groupsum[1 * NBATCH + bb] * (1.0f / NPTS);
                    total += fmaxf(mean_rec, mean_dat);
                }
                out[0] = total * (1.0f / NBATCH);
                // reset counters for next graph replay
                #pragma unroll
                for (int gg = 0; gg < GROUPS; ++gg) g_cnt[gg] = 0u;
                g_cnt2 = 0u;
            }
        }
    }
}

extern "C" void kernel_launch(void* const* d_in, const int* in_sizes, int n_in,
                              void* d_out, int out_size) {
    const float* rec  = (const float*)d_in[0];   // (B, N, 3) fp32
    const float* data = (const float*)d_in[1];   // (B, M, 3) fp32
    float* out = (float*)d_out;

    dim3 grid(CHUNKS * SLICES, NBATCH, 2);       // 256 x 4 x 2 = 2048 blocks
    chamfer_main<<<grid, THREADS>>>(rec, data, out);
}

// round 8
// speedup vs baseline: 1.0677x; 1.0677x over previous
#include <cuda_runtime.h>

#define NBATCH   4
#define NPTS     8192
#define THREADS  256
#define QPT      4                       // queries per thread
#define QBLK     (THREADS * QPT)         // 1024 queries per block
#define CHUNKS   (NPTS / QBLK)           // 8 query chunks
#define SLICES   32                      // db split
#define DBS      (NPTS / SLICES)         // 256 db points per block
#define GROUPS   (2 * NBATCH)            // 8 (dir,b) groups
#define BLOCKS_PER_GROUP (CHUNKS * SLICES)    // 256

// Per-query clamped slice-min: [group][slice][query]. Every slot is
// overwritten each launch -> deterministic, no init needed. (8 MB)
__device__ float        g_min[GROUPS][SLICES][NPTS];
__device__ float        g_groupsum[GROUPS];
__device__ unsigned int g_cnt[GROUPS];   // zero-init; reset by final finisher
__device__ unsigned int g_cnt2;          // zero-init; reset by final finisher

typedef unsigned long long ull;

__device__ __forceinline__ ull ffma2(ull a, ull b, ull c) {
    ull d;
    asm("fma.rn.f32x2 %0, %1, %2, %3;" : "=l"(d) : "l"(a), "l"(b), "l"(c));
    return d;
}
__device__ __forceinline__ ull pack2(float lo, float hi) {
    ull d;
    asm("mov.b64 %0, {%1, %2};" : "=l"(d) : "f"(lo), "f"(hi));
    return d;
}
__device__ __forceinline__ float2 unpack2(ull v) {
    float2 r;
    asm("mov.b64 {%0, %1}, %2;" : "=f"(r.x), "=f"(r.y) : "l"(v));
    return r;
}

__global__ __launch_bounds__(THREADS, 2)
void chamfer_main(const float* __restrict__ rec,
                  const float* __restrict__ data,
                  float* __restrict__ out) {
    __shared__ float s0[DBS];
    __shared__ float s1[DBS];
    __shared__ float s2[DBS];
    __shared__ float sn[DBS];
    __shared__ float red[THREADS];
    __shared__ int   s_flag;

    const int tid   = threadIdx.x;
    const int slice = blockIdx.x & (SLICES - 1);
    const int chunk = blockIdx.x >> 5;            // 0..CHUNKS-1
    const int b     = blockIdx.y;
    const int dir   = blockIdx.z;
    const int group = dir * NBATCH + b;

    // dir 0: queries = rec, database = data   (rec_dist)
    // dir 1: queries = data, database = rec   (data_dist)
    const float* __restrict__ qry = dir ? data : rec;
    const float* __restrict__ db  = dir ? rec  : data;

    // ---- Load this db slice into SMEM (SoA + precomputed norms) ----
    const float* dbb = db + ((size_t)b * NPTS + slice * DBS) * 3;
    if (tid < DBS) {
        float x = dbb[3 * tid + 0];
        float y = dbb[3 * tid + 1];
        float z = dbb[3 * tid + 2];
        s0[tid] = x;
        s1[tid] = y;
        s2[tid] = z;
        sn[tid] = fmaf(x, x, fmaf(y, y, z * z));
    }

    // ---- Per-thread query points (4, coalesced across warp) ----
    float q2[QPT];
    ull A0[QPT], A1[QPT], A2[QPT];
    #pragma unroll
    for (int q = 0; q < QPT; ++q) {
        int qi = chunk * QBLK + q * THREADS + tid;
        const float* qp = qry + ((size_t)b * NPTS + qi) * 3;
        float qx = qp[0], qy = qp[1], qz = qp[2];
        q2[q] = fmaf(qx, qx, fmaf(qy, qy, qz * qz));
        A0[q] = pack2(-2.0f * qx, -2.0f * qx);
        A1[q] = pack2(-2.0f * qy, -2.0f * qy);
        A2[q] = pack2(-2.0f * qz, -2.0f * qz);
    }

    __syncthreads();

    // ---- Main loop: min_j ( ||y_j||^2 - 2 x . y_j )
    //      4 db points / step, 4 queries / thread.
    //      Software-pipelined: next step's LDS.128s issue before this step's
    //      math so the 29-cycle LDS latency is hidden inside the math. ----
    float m0[QPT], m1[QPT], m2[QPT], m3[QPT];
    #pragma unroll
    for (int q = 0; q < QPT; ++q) { m0[q] = m1[q] = m2[q] = m3[q] = 1e30f; }

    ulonglong2 p0 = *reinterpret_cast<const ulonglong2*>(s0);
    ulonglong2 p1 = *reinterpret_cast<const ulonglong2*>(s1);
    ulonglong2 p2 = *reinterpret_cast<const ulonglong2*>(s2);
    ulonglong2 pn = *reinterpret_cast<const ulonglong2*>(sn);

    #pragma unroll 2
    for (int j = 4; j < DBS; j += 4) {
        // prefetch next 4 db points
        ulonglong2 n0 = *reinterpret_cast<const ulonglong2*>(s0 + j);
        ulonglong2 n1 = *reinterpret_cast<const ulonglong2*>(s1 + j);
        ulonglong2 n2 = *reinterpret_cast<const ulonglong2*>(s2 + j);
        ulonglong2 nn = *reinterpret_cast<const ulonglong2*>(sn + j);

        #pragma unroll
        for (int q = 0; q < QPT; ++q) {
            ull accA = ffma2(A2[q], p2.x, pn.x);
            accA     = ffma2(A1[q], p1.x, accA);
            accA     = ffma2(A0[q], p0.x, accA);

            ull accB = ffma2(A2[q], p2.y, pn.y);
            accB     = ffma2(A1[q], p1.y, accB);
            accB     = ffma2(A0[q], p0.y, accB);

            float2 fa = unpack2(accA);
            float2 fb = unpack2(accB);
            m0[q] = fminf(m0[q], fa.x);
            m1[q] = fminf(m1[q], fa.y);
            m2[q] = fminf(m2[q], fb.x);
            m3[q] = fminf(m3[q], fb.y);
        }

        p0 = n0; p1 = n1; p2 = n2; pn = nn;
    }

    // last 4 db points (already in registers)
    #pragma unroll
    for (int q = 0; q < QPT; ++q) {
        ull accA = ffma2(A2[q], p2.x, pn.x);
        accA     = ffma2(A1[q], p1.x, accA);
        accA     = ffma2(A0[q], p0.x, accA);

        ull accB = ffma2(A2[q], p2.y, pn.y);
        accB     = ffma2(A1[q], p1.y, accB);
        accB     = ffma2(A0[q], p0.y, accB);

        float2 fa = unpack2(accA);
        float2 fb = unpack2(accB);
        m0[q] = fminf(m0[q], fa.x);
        m1[q] = fminf(m1[q], fa.y);
        m2[q] = fminf(m2[q], fb.x);
        m3[q] = fminf(m3[q], fb.y);
    }

    // ---- Per-query clamped slice-min -> global slot (coalesced stores) ----
    const int base = chunk * QBLK + tid;
    #pragma unroll
    for (int q = 0; q < QPT; ++q) {
        float mmin = fminf(fminf(m0[q], m1[q]), fminf(m2[q], m3[q]));
        float dist = fmaxf(q2[q] + mmin, 0.0f);   // clamp commutes with min
        g_min[group][slice][base + q * THREADS] = dist;
    }

    // ---- Fused reduce: last block of each group reduces that group ----
    if (tid == 0) {
        __threadfence();
        unsigned int t = atomicAdd(&g_cnt[group], 1u);
        s_flag = (t == BLOCKS_PER_GROUP - 1) ? 1 : 0;
    }
    __syncthreads();

    if (s_flag) {
        __threadfence();   // acquire: other blocks' g_min writes are visible
        float s = 0.0f;
        for (int q = tid * 4; q < NPTS; q += THREADS * 4) {
            float4 m = *reinterpret_cast<const float4*>(&g_min[group][0][q]);
            #pragma unroll
            for (int e = 1; e < SLICES; ++e) {
                float4 v = *reinterpret_cast<const float4*>(&g_min[group][e][q]);
                m.x = fminf(m.x, v.x);
                m.y = fminf(m.y, v.y);
                m.z = fminf(m.z, v.z);
                m.w = fminf(m.w, v.w);
            }
            s += (m.x + m.y) + (m.z + m.w);
        }
        red[tid] = s;
        __syncthreads();
        #pragma unroll
        for (int st = THREADS / 2; st > 0; st >>= 1) {
            if (tid < st) red[tid] += red[tid + st];
            __syncthreads();
        }
        if (tid == 0) {
            g_groupsum[group] = red[0];
            __threadfence();
            unsigned int t2 = atomicAdd(&g_cnt2, 1u);
            if (t2 == GROUPS - 1) {
                __threadfence();
                float total = 0.0f;
                #pragma unroll
                for (int bb = 0; bb < NBATCH; ++bb) {
                    float mean_rec = g_groupsum[0 * NBATCH + bb] * (1.0f / NPTS);
                    float mean_dat = g_groupsum[1 * NBATCH + bb] * (1.0f / NPTS);
                    total += fmaxf(mean_rec, mean_dat);
                }
                out[0] = total * (1.0f / NBATCH);
                // reset counters for next graph replay
                #pragma unroll
                for (int gg = 0; gg < GROUPS; ++gg) g_cnt[gg] = 0u;
                g_cnt2 = 0u;
            }
        }
    }
}

extern "C" void kernel_launch(void* const* d_in, const int* in_sizes, int n_in,
                              void* d_out, int out_size) {
    const float* rec  = (const float*)d_in[0];   // (B, N, 3) fp32
    const float* data = (const float*)d_in[1];   // (B, M, 3) fp32
    float* out = (float*)d_out;

    dim3 grid(CHUNKS * SLICES, NBATCH, 2);       // 256 x 4 x 2 = 2048 blocks
    chamfer_main<<<grid, THREADS>>>(rec, data, out);
}